// round 1
// baseline (speedup 1.0000x reference)
#include <cuda_runtime.h>
#include <cuda_bf16.h>
#include <math.h>

// Problem constants
#define Hq    12
#define HKV   2
#define NG    6          // Hq / HKV
#define Dh    128
#define HID   1536
#define Bc    4
#define Sc    2048
#define Tn    (Bc*Sc)    // 8192 tokens
#define NQKV  2048       // Hq*Dh + 2*HKV*Dh
#define NSLOTS 16384
#define OUT_ELEMS   ((size_t)Tn*HID)          // 12582912
#define CACHE_ELEMS ((size_t)NSLOTS*HKV*Dh)   // 4194304

// Scratch (device globals; no runtime allocation allowed)
__device__ float g_qkv[(size_t)Tn * NQKV];    // 67 MB
__device__ float g_attn[(size_t)Tn * HID];    // 50 MB

// ---------------------------------------------------------------------------
// GEMM C[M,N] = A[M,K] @ B[N,K]^T (+ bias[N]).  64x64x16 tiles, 4x4 microtile.
// M,N multiples of 64; K multiple of 16.
// ---------------------------------------------------------------------------
#define TKk 16
__global__ void gemm_nt_kernel(const float* __restrict__ A,
                               const float* __restrict__ Bw,
                               const float* __restrict__ bias,
                               float* __restrict__ C,
                               int M, int N, int K) {
    __shared__ float As[64][TKk + 1];
    __shared__ float Bs[64][TKk + 1];
    const int tx = threadIdx.x, ty = threadIdx.y;
    const int tid = ty * 16 + tx;
    const int n0 = blockIdx.x * 64;
    const int m0 = blockIdx.y * 64;

    const int rload = tid >> 2;          // 0..63 tile row
    const int kg = (tid & 3) * 4;        // 0,4,8,12

    float acc[4][4];
#pragma unroll
    for (int i = 0; i < 4; i++)
#pragma unroll
        for (int j = 0; j < 4; j++) acc[i][j] = 0.f;

    for (int k0 = 0; k0 < K; k0 += TKk) {
        float4 av = *(const float4*)(A  + (size_t)(m0 + rload) * K + k0 + kg);
        float4 bv = *(const float4*)(Bw + (size_t)(n0 + rload) * K + k0 + kg);
        As[rload][kg]   = av.x; As[rload][kg+1] = av.y;
        As[rload][kg+2] = av.z; As[rload][kg+3] = av.w;
        Bs[rload][kg]   = bv.x; Bs[rload][kg+1] = bv.y;
        Bs[rload][kg+2] = bv.z; Bs[rload][kg+3] = bv.w;
        __syncthreads();
#pragma unroll
        for (int kk = 0; kk < TKk; kk++) {
            float a[4], b[4];
#pragma unroll
            for (int i = 0; i < 4; i++) a[i] = As[ty * 4 + i][kk];
#pragma unroll
            for (int j = 0; j < 4; j++) b[j] = Bs[tx * 4 + j][kk];
#pragma unroll
            for (int i = 0; i < 4; i++)
#pragma unroll
                for (int j = 0; j < 4; j++) acc[i][j] = fmaf(a[i], b[j], acc[i][j]);
        }
        __syncthreads();
    }

#pragma unroll
    for (int i = 0; i < 4; i++) {
        const size_t crow = (size_t)(m0 + ty * 4 + i) * N + n0;
#pragma unroll
        for (int j = 0; j < 4; j++) {
            float v = acc[i][j];
            if (bias) v += bias[n0 + tx * 4 + j];
            C[crow + tx * 4 + j] = v;
        }
    }
}

// ---------------------------------------------------------------------------
// RoPE (in place on g_qkv q,k heads) + scatter rotated k and raw v to caches.
// One block per token.
// ---------------------------------------------------------------------------
__global__ void rope_scatter_kernel(float* __restrict__ qkv,
                                    const float* __restrict__ cosb,
                                    const float* __restrict__ sinb,
                                    const int* __restrict__ slot,
                                    float* __restrict__ kc,
                                    float* __restrict__ vc) {
    const int r = blockIdx.x;                 // token 0..8191
    float* row = qkv + (size_t)r * NQKV;
    const float* cr = cosb + (size_t)r * Dh;
    const float* sr = sinb + (size_t)r * Dh;
    const int s = slot[r];

    // 14 rotated heads (12 q + 2 k) x 64 pairs = 896
    for (int idx = threadIdx.x; idx < 14 * 64; idx += blockDim.x) {
        const int head = idx >> 6;
        const int d = idx & 63;
        float* hp = row + head * Dh;
        const float x1 = hp[d], x2 = hp[d + 64];
        const float c1 = cr[d], s1 = sr[d];
        const float c2 = cr[d + 64], s2 = sr[d + 64];
        const float o1 = x1 * c1 - x2 * s1;
        const float o2 = x2 * c2 + x1 * s2;
        hp[d] = o1;
        hp[d + 64] = o2;
        if (head >= Hq) {
            const int kh = head - Hq;
            float* kdst = kc + ((size_t)s * HKV + kh) * Dh;
            kdst[d] = o1;
            kdst[d + 64] = o2;
        }
    }
    // v copy: HKV*Dh = 256 elements
    for (int idx = threadIdx.x; idx < HKV * Dh; idx += blockDim.x) {
        vc[(size_t)s * (HKV * Dh) + idx] = row[Hq * Dh + HKV * Dh + idx];
    }
}

// ---------------------------------------------------------------------------
// Causal GQA flash attention.
// Grid: (S/64, Hq, B). Block: (16,16). Dynamic smem ~116KB.
// Reads rotated q,k and v straight from g_qkv; writes g_attn [T, HID].
// ---------------------------------------------------------------------------
#define QSTR 132
#define SSTR 65
#define ATT_SMEM_FLOATS (3 * 64 * QSTR + 64 * SSTR + 3 * 64)
__global__ void attn_kernel(const float* __restrict__ qkv, float* __restrict__ out) {
    extern __shared__ float sm[];
    float* Qs = sm;
    float* Ks = Qs + 64 * QSTR;
    float* Vs = Ks + 64 * QSTR;
    float* Ss = Vs + 64 * QSTR;
    float* mrow = Ss + 64 * SSTR;
    float* lrow = mrow + 64;
    float* arow = lrow + 64;

    const int qt = blockIdx.x, h = blockIdx.y, b = blockIdx.z;
    const int kh = h / NG;
    const int tx = threadIdx.x, ty = threadIdx.y;
    const int tid = ty * 16 + tx;
    const int q0 = qt * 64;
    const int rowbase = b * Sc;
    const float scale = 0.08838834764831845f;   // 1/sqrt(128)

    // Load Q tile
    for (int i = tid; i < 64 * 128; i += 256) {
        const int r = i >> 7, d = i & 127;
        Qs[r * QSTR + d] = qkv[(size_t)(rowbase + q0 + r) * NQKV + h * Dh + d];
    }
    if (tid < 64) { mrow[tid] = -1e30f; lrow[tid] = 0.f; }

    float o[4][8];
#pragma unroll
    for (int i = 0; i < 4; i++)
#pragma unroll
        for (int c = 0; c < 8; c++) o[i][c] = 0.f;
    __syncthreads();

    for (int kt = 0; kt <= qt; kt++) {
        const int k0 = kt * 64;
        for (int i = tid; i < 64 * 128; i += 256) {
            const int r = i >> 7, d = i & 127;
            const size_t rb = (size_t)(rowbase + k0 + r) * NQKV;
            Ks[r * QSTR + d] = qkv[rb + Hq * Dh + kh * Dh + d];
            Vs[r * QSTR + d] = qkv[rb + Hq * Dh + HKV * Dh + kh * Dh + d];
        }
        __syncthreads();

        // scores 64x64, 4x4 per thread
        float acc[4][4];
#pragma unroll
        for (int i = 0; i < 4; i++)
#pragma unroll
            for (int j = 0; j < 4; j++) acc[i][j] = 0.f;

        for (int kk = 0; kk < 128; kk++) {
            float a[4], bb[4];
#pragma unroll
            for (int i = 0; i < 4; i++) a[i] = Qs[(ty * 4 + i) * QSTR + kk];
#pragma unroll
            for (int j = 0; j < 4; j++) bb[j] = Ks[(tx * 4 + j) * QSTR + kk];
#pragma unroll
            for (int i = 0; i < 4; i++)
#pragma unroll
                for (int j = 0; j < 4; j++) acc[i][j] = fmaf(a[i], bb[j], acc[i][j]);
        }
#pragma unroll
        for (int i = 0; i < 4; i++) {
            const int qr = q0 + ty * 4 + i;
#pragma unroll
            for (int j = 0; j < 4; j++) {
                const int kr = k0 + tx * 4 + j;
                Ss[(ty * 4 + i) * SSTR + tx * 4 + j] =
                    (kr <= qr) ? acc[i][j] * scale : -1e30f;
            }
        }
        __syncthreads();

        // online softmax per row
        if (tid < 64) {
            float mo = mrow[tid], mn = mo;
#pragma unroll 8
            for (int j = 0; j < 64; j++) mn = fmaxf(mn, Ss[tid * SSTR + j]);
            const float al = __expf(mo - mn);
            float l = lrow[tid] * al;
#pragma unroll 8
            for (int j = 0; j < 64; j++) {
                const float p = __expf(Ss[tid * SSTR + j] - mn);
                Ss[tid * SSTR + j] = p;
                l += p;
            }
            mrow[tid] = mn; lrow[tid] = l; arow[tid] = al;
        }
        __syncthreads();

        // rescale o and accumulate P @ V (4 rows x 8 cols per thread)
#pragma unroll
        for (int i = 0; i < 4; i++) {
            const float al = arow[ty * 4 + i];
#pragma unroll
            for (int c = 0; c < 8; c++) o[i][c] *= al;
        }
        for (int j = 0; j < 64; j++) {
            float v[8];
#pragma unroll
            for (int c = 0; c < 8; c++) v[c] = Vs[j * QSTR + tx * 8 + c];
#pragma unroll
            for (int i = 0; i < 4; i++) {
                const float p = Ss[(ty * 4 + i) * SSTR + j];
#pragma unroll
                for (int c = 0; c < 8; c++) o[i][c] = fmaf(p, v[c], o[i][c]);
            }
        }
        __syncthreads();
    }

    // normalize + write
#pragma unroll
    for (int i = 0; i < 4; i++) {
        const int r = ty * 4 + i;
        const float inv = 1.0f / lrow[r];
        const size_t obase = (size_t)(rowbase + q0 + r) * HID + h * Dh + tx * 8;
#pragma unroll
        for (int c = 0; c < 8; c++) out[obase + c] = o[i][c] * inv;
    }
}

// ---------------------------------------------------------------------------
// kernel_launch
// inputs: 0 x, 1 cos, 2 sin, 3 kv_cache_k, 4 kv_cache_v, 5 slot_mapping,
//         6 Wqkv, 7 bqkv, 8 Wo, 9 is_prefill
// d_out: [out (T*HID) | kc (NSLOTS*HKV*Dh) | vc (NSLOTS*HKV*Dh)] fp32
// ---------------------------------------------------------------------------
extern "C" void kernel_launch(void* const* d_in, const int* in_sizes, int n_in,
                              void* d_out, int out_size) {
    const float* x    = (const float*)d_in[0];
    const float* cosb = (const float*)d_in[1];
    const float* sinb = (const float*)d_in[2];
    const float* kci  = (const float*)d_in[3];
    const float* vci  = (const float*)d_in[4];
    const int*   slot = (const int*)d_in[5];
    const float* Wqkv = (const float*)d_in[6];
    const float* bqkv = (const float*)d_in[7];
    const float* Wo   = (const float*)d_in[8];

    float* out = (float*)d_out;
    float* kc  = out + OUT_ELEMS;
    float* vc  = kc + CACHE_ELEMS;

    float* qkv;  cudaGetSymbolAddress((void**)&qkv,  g_qkv);
    float* attn; cudaGetSymbolAddress((void**)&attn, g_attn);

    static bool attr_set = false;
    if (!attr_set) {
        cudaFuncSetAttribute(attn_kernel,
                             cudaFuncAttributeMaxDynamicSharedMemorySize,
                             ATT_SMEM_FLOATS * (int)sizeof(float));
        attr_set = true;
    }

    // 1. seed caches with the input caches (slots not in slot_mapping stay 0)
    cudaMemcpyAsync(kc, kci, CACHE_ELEMS * sizeof(float), cudaMemcpyDeviceToDevice);
    cudaMemcpyAsync(vc, vci, CACHE_ELEMS * sizeof(float), cudaMemcpyDeviceToDevice);

    // 2. QKV projection: [T, NQKV] = x[T, HID] @ Wqkv[NQKV, HID]^T + b
    {
        dim3 grid(NQKV / 64, Tn / 64);
        dim3 blk(16, 16);
        gemm_nt_kernel<<<grid, blk>>>(x, Wqkv, bqkv, qkv, Tn, NQKV, HID);
    }

    // 3. RoPE in place + cache scatter
    rope_scatter_kernel<<<Tn, 256>>>(qkv, cosb, sinb, slot, kc, vc);

    // 4. causal GQA flash attention
    {
        dim3 grid(Sc / 64, Hq, Bc);
        dim3 blk(16, 16);
        attn_kernel<<<grid, blk, ATT_SMEM_FLOATS * sizeof(float)>>>(qkv, attn);
    }

    // 5. output projection: out[T, HID] = attn[T, HID] @ Wo[HID, HID]^T
    {
        dim3 grid(HID / 64, Tn / 64);
        dim3 blk(16, 16);
        gemm_nt_kernel<<<grid, blk>>>(attn, Wo, nullptr, out, Tn, HID, HID);
    }
}

// round 3
// speedup vs baseline: 1.4886x; 1.4886x over previous
#include <cuda_runtime.h>
#include <cuda_bf16.h>
#include <cstdint>
#include <math.h>

// Problem constants
#define Hq    12
#define HKV   2
#define NG    6          // Hq / HKV
#define Dh    128
#define HID   1536
#define Bc    4
#define Sc    2048
#define Tn    (Bc*Sc)    // 8192 tokens
#define NQKV  2048       // Hq*Dh + 2*HKV*Dh
#define NSLOTS 16384
#define OUT_ELEMS   ((size_t)Tn*HID)          // 12582912
#define CACHE_ELEMS ((size_t)NSLOTS*HKV*Dh)   // 4194304

// Scratch (device globals; no runtime allocation allowed)
__device__ float g_qkv[(size_t)Tn * NQKV];    // 67 MB
__device__ float g_attn[(size_t)Tn * HID];    // 50 MB

// ===========================================================================
// TF32 helpers (portable to plain sm_103 target: no 'a'-gated instructions)
// ===========================================================================
__device__ __forceinline__ float to_tf32(float x) {
    float y;
    asm("cvt.rna.tf32.f32 %0, %1;" : "=f"(y) : "f"(x));
    return y;
}

__device__ __forceinline__ void mma_tf32_16x8x8(
    float& d0, float& d1, float& d2, float& d3,
    float a0, float a1, float a2, float a3,
    float b0, float b1)
{
    uint32_t A0 = __float_as_uint(a0), A1 = __float_as_uint(a1);
    uint32_t A2 = __float_as_uint(a2), A3 = __float_as_uint(a3);
    uint32_t B0 = __float_as_uint(b0), B1 = __float_as_uint(b1);
    asm volatile(
        "mma.sync.aligned.m16n8k8.row.col.f32.tf32.tf32.f32 "
        "{%0,%1,%2,%3}, {%4,%5,%6,%7}, {%8,%9}, {%0,%1,%2,%3};"
        : "+f"(d0), "+f"(d1), "+f"(d2), "+f"(d3)
        : "r"(A0), "r"(A1), "r"(A2), "r"(A3), "r"(B0), "r"(B1));
}

// ===========================================================================
// TF32 tensor-core GEMM: C[M,N] = A[M,K] @ B[N,K]^T (+ bias[N])
// CTA tile 128x128, BK=32, 8 warps in 2x4 (warp tile 64x32), double-buffered.
// Smem stride 36 floats -> conflict-free fragment loads (bank = 4*row+k).
// M,N multiples of 128, K multiple of 32.
// ===========================================================================
#define GSTR 36
#define GBUF (128 * GSTR)                 // floats per tile buffer
#define G_SMEM_FLOATS (4 * GBUF)          // As[2] + Bs[2]

__global__ __launch_bounds__(256, 2) void gemm_mma_kernel(
    const float* __restrict__ A, const float* __restrict__ Bw,
    const float* __restrict__ bias, float* __restrict__ C,
    int M, int N, int K)
{
    extern __shared__ float smem[];
    float* As = smem;                    // [2][128][GSTR]
    float* Bs = smem + 2 * GBUF;

    const int tid  = threadIdx.x;
    const int wid  = tid >> 5;
    const int lane = tid & 31;
    const int gid  = lane >> 2;          // group id 0..7
    const int tig  = lane & 3;           // thread in group 0..3

    const int m0 = blockIdx.y * 128;
    const int n0 = blockIdx.x * 128;
    const int wm0 = (wid >> 2) * 64;     // warp M offset in tile
    const int wn0 = (wid & 3) * 32;      // warp N offset in tile

    // per-thread gmem staging (4 float4 each for A and B)
    float4 ar[4], br[4];

    float acc[4][4][4];
#pragma unroll
    for (int mi = 0; mi < 4; mi++)
#pragma unroll
        for (int ni = 0; ni < 4; ni++)
#pragma unroll
            for (int r = 0; r < 4; r++) acc[mi][ni][r] = 0.f;

    const int nchunks = K >> 5;

    // ---- prologue: load chunk 0 and store to buffer 0
#pragma unroll
    for (int i = 0; i < 4; i++) {
        const int idx = tid + i * 256;
        const int r  = idx >> 3;
        const int cg = (idx & 7) << 2;
        ar[i] = *(const float4*)(A  + (size_t)(m0 + r) * K + cg);
        br[i] = *(const float4*)(Bw + (size_t)(n0 + r) * K + cg);
    }
#pragma unroll
    for (int i = 0; i < 4; i++) {
        const int idx = tid + i * 256;
        const int r  = idx >> 3;
        const int cg = (idx & 7) << 2;
        float* pa = As + r * GSTR + cg;
        pa[0] = to_tf32(ar[i].x); pa[1] = to_tf32(ar[i].y);
        pa[2] = to_tf32(ar[i].z); pa[3] = to_tf32(ar[i].w);
        float* pb = Bs + r * GSTR + cg;
        pb[0] = to_tf32(br[i].x); pb[1] = to_tf32(br[i].y);
        pb[2] = to_tf32(br[i].z); pb[3] = to_tf32(br[i].w);
    }
    __syncthreads();

    int p = 0;
    for (int c = 0; c < nchunks; c++) {
        const bool more = (c + 1) < nchunks;
        if (more) {
            const int kc = (c + 1) << 5;
#pragma unroll
            for (int i = 0; i < 4; i++) {
                const int idx = tid + i * 256;
                const int r  = idx >> 3;
                const int cg = (idx & 7) << 2;
                ar[i] = *(const float4*)(A  + (size_t)(m0 + r) * K + kc + cg);
                br[i] = *(const float4*)(Bw + (size_t)(n0 + r) * K + kc + cg);
            }
        }

        // ---- compute on buffer p
        const float* Ab = As + p * GBUF;
        const float* Bb = Bs + p * GBUF;
#pragma unroll
        for (int ks = 0; ks < 4; ks++) {
            const int kk = ks * 8;
            float afr[4][4];
#pragma unroll
            for (int mi = 0; mi < 4; mi++) {
                const int r = wm0 + mi * 16 + gid;
                const int cA = kk + tig;
                afr[mi][0] = Ab[r * GSTR + cA];
                afr[mi][1] = Ab[(r + 8) * GSTR + cA];
                afr[mi][2] = Ab[r * GSTR + cA + 4];
                afr[mi][3] = Ab[(r + 8) * GSTR + cA + 4];
            }
#pragma unroll
            for (int ni = 0; ni < 4; ni++) {
                const int rB = wn0 + ni * 8 + gid;
                const int cB = kk + tig;
                const float b0 = Bb[rB * GSTR + cB];
                const float b1 = Bb[rB * GSTR + cB + 4];
#pragma unroll
                for (int mi = 0; mi < 4; mi++) {
                    mma_tf32_16x8x8(acc[mi][ni][0], acc[mi][ni][1],
                                    acc[mi][ni][2], acc[mi][ni][3],
                                    afr[mi][0], afr[mi][1], afr[mi][2], afr[mi][3],
                                    b0, b1);
                }
            }
        }

        if (more) {
            float* Aw = As + (p ^ 1) * GBUF;
            float* Bww = Bs + (p ^ 1) * GBUF;
#pragma unroll
            for (int i = 0; i < 4; i++) {
                const int idx = tid + i * 256;
                const int r  = idx >> 3;
                const int cg = (idx & 7) << 2;
                float* pa = Aw + r * GSTR + cg;
                pa[0] = to_tf32(ar[i].x); pa[1] = to_tf32(ar[i].y);
                pa[2] = to_tf32(ar[i].z); pa[3] = to_tf32(ar[i].w);
                float* pb = Bww + r * GSTR + cg;
                pb[0] = to_tf32(br[i].x); pb[1] = to_tf32(br[i].y);
                pb[2] = to_tf32(br[i].z); pb[3] = to_tf32(br[i].w);
            }
        }
        __syncthreads();
        p ^= 1;
    }

    // ---- epilogue: float2 stores, optional bias
#pragma unroll
    for (int mi = 0; mi < 4; mi++) {
        const int row = m0 + wm0 + mi * 16 + gid;
#pragma unroll
        for (int ni = 0; ni < 4; ni++) {
            const int col = n0 + wn0 + ni * 8 + 2 * tig;
            float b0 = 0.f, b1 = 0.f;
            if (bias) { b0 = bias[col]; b1 = bias[col + 1]; }
            float2 v0 = make_float2(acc[mi][ni][0] + b0, acc[mi][ni][1] + b1);
            float2 v1 = make_float2(acc[mi][ni][2] + b0, acc[mi][ni][3] + b1);
            *(float2*)(C + (size_t)row * N + col)       = v0;
            *(float2*)(C + (size_t)(row + 8) * N + col) = v1;
        }
    }
}

// ---------------------------------------------------------------------------
// RoPE (in place on g_qkv q,k heads) + scatter rotated k and raw v to caches.
// ---------------------------------------------------------------------------
__global__ void rope_scatter_kernel(float* __restrict__ qkv,
                                    const float* __restrict__ cosb,
                                    const float* __restrict__ sinb,
                                    const int* __restrict__ slot,
                                    float* __restrict__ kc,
                                    float* __restrict__ vc) {
    const int r = blockIdx.x;
    float* row = qkv + (size_t)r * NQKV;
    const float* cr = cosb + (size_t)r * Dh;
    const float* sr = sinb + (size_t)r * Dh;
    const int s = slot[r];

    for (int idx = threadIdx.x; idx < 14 * 64; idx += blockDim.x) {
        const int head = idx >> 6;
        const int d = idx & 63;
        float* hp = row + head * Dh;
        const float x1 = hp[d], x2 = hp[d + 64];
        const float c1 = cr[d], s1 = sr[d];
        const float c2 = cr[d + 64], s2 = sr[d + 64];
        const float o1 = x1 * c1 - x2 * s1;
        const float o2 = x2 * c2 + x1 * s2;
        hp[d] = o1;
        hp[d + 64] = o2;
        if (head >= Hq) {
            const int kh = head - Hq;
            float* kdst = kc + ((size_t)s * HKV + kh) * Dh;
            kdst[d] = o1;
            kdst[d + 64] = o2;
        }
    }
    for (int idx = threadIdx.x; idx < HKV * Dh; idx += blockDim.x) {
        vc[(size_t)s * (HKV * Dh) + idx] = row[Hq * Dh + HKV * Dh + idx];
    }
}

// ---------------------------------------------------------------------------
// Causal GQA flash attention (fp32 SIMT — tensorize in a later round).
// ---------------------------------------------------------------------------
#define QSTR 132
#define SSTR 65
#define ATT_SMEM_FLOATS (3 * 64 * QSTR + 64 * SSTR + 3 * 64)
__global__ void attn_kernel(const float* __restrict__ qkv, float* __restrict__ out) {
    extern __shared__ float sm[];
    float* Qs = sm;
    float* Ks = Qs + 64 * QSTR;
    float* Vs = Ks + 64 * QSTR;
    float* Ss = Vs + 64 * QSTR;
    float* mrow = Ss + 64 * SSTR;
    float* lrow = mrow + 64;
    float* arow = lrow + 64;

    const int qt = blockIdx.x, h = blockIdx.y, b = blockIdx.z;
    const int kh = h / NG;
    const int tx = threadIdx.x, ty = threadIdx.y;
    const int tid = ty * 16 + tx;
    const int q0 = qt * 64;
    const int rowbase = b * Sc;
    const float scale = 0.08838834764831845f;

    for (int i = tid; i < 64 * 128; i += 256) {
        const int r = i >> 7, d = i & 127;
        Qs[r * QSTR + d] = qkv[(size_t)(rowbase + q0 + r) * NQKV + h * Dh + d];
    }
    if (tid < 64) { mrow[tid] = -1e30f; lrow[tid] = 0.f; }

    float o[4][8];
#pragma unroll
    for (int i = 0; i < 4; i++)
#pragma unroll
        for (int c = 0; c < 8; c++) o[i][c] = 0.f;
    __syncthreads();

    for (int kt = 0; kt <= qt; kt++) {
        const int k0 = kt * 64;
        for (int i = tid; i < 64 * 128; i += 256) {
            const int r = i >> 7, d = i & 127;
            const size_t rb = (size_t)(rowbase + k0 + r) * NQKV;
            Ks[r * QSTR + d] = qkv[rb + Hq * Dh + kh * Dh + d];
            Vs[r * QSTR + d] = qkv[rb + Hq * Dh + HKV * Dh + kh * Dh + d];
        }
        __syncthreads();

        float acc[4][4];
#pragma unroll
        for (int i = 0; i < 4; i++)
#pragma unroll
            for (int j = 0; j < 4; j++) acc[i][j] = 0.f;

        for (int kk = 0; kk < 128; kk++) {
            float a[4], bb[4];
#pragma unroll
            for (int i = 0; i < 4; i++) a[i] = Qs[(ty * 4 + i) * QSTR + kk];
#pragma unroll
            for (int j = 0; j < 4; j++) bb[j] = Ks[(tx * 4 + j) * QSTR + kk];
#pragma unroll
            for (int i = 0; i < 4; i++)
#pragma unroll
                for (int j = 0; j < 4; j++) acc[i][j] = fmaf(a[i], bb[j], acc[i][j]);
        }
#pragma unroll
        for (int i = 0; i < 4; i++) {
            const int qr = q0 + ty * 4 + i;
#pragma unroll
            for (int j = 0; j < 4; j++) {
                const int kr = k0 + tx * 4 + j;
                Ss[(ty * 4 + i) * SSTR + tx * 4 + j] =
                    (kr <= qr) ? acc[i][j] * scale : -1e30f;
            }
        }
        __syncthreads();

        if (tid < 64) {
            float mo = mrow[tid], mn = mo;
#pragma unroll 8
            for (int j = 0; j < 64; j++) mn = fmaxf(mn, Ss[tid * SSTR + j]);
            const float al = __expf(mo - mn);
            float l = lrow[tid] * al;
#pragma unroll 8
            for (int j = 0; j < 64; j++) {
                const float p = __expf(Ss[tid * SSTR + j] - mn);
                Ss[tid * SSTR + j] = p;
                l += p;
            }
            mrow[tid] = mn; lrow[tid] = l; arow[tid] = al;
        }
        __syncthreads();

#pragma unroll
        for (int i = 0; i < 4; i++) {
            const float al = arow[ty * 4 + i];
#pragma unroll
            for (int c = 0; c < 8; c++) o[i][c] *= al;
        }
        for (int j = 0; j < 64; j++) {
            float v[8];
#pragma unroll
            for (int c = 0; c < 8; c++) v[c] = Vs[j * QSTR + tx * 8 + c];
#pragma unroll
            for (int i = 0; i < 4; i++) {
                const float p = Ss[(ty * 4 + i) * SSTR + j];
#pragma unroll
                for (int c = 0; c < 8; c++) o[i][c] = fmaf(p, v[c], o[i][c]);
            }
        }
        __syncthreads();
    }

#pragma unroll
    for (int i = 0; i < 4; i++) {
        const int r = ty * 4 + i;
        const float inv = 1.0f / lrow[r];
        const size_t obase = (size_t)(rowbase + q0 + r) * HID + h * Dh + tx * 8;
#pragma unroll
        for (int c = 0; c < 8; c++) out[obase + c] = o[i][c] * inv;
    }
}

// ---------------------------------------------------------------------------
// kernel_launch
// ---------------------------------------------------------------------------
extern "C" void kernel_launch(void* const* d_in, const int* in_sizes, int n_in,
                              void* d_out, int out_size) {
    const float* x    = (const float*)d_in[0];
    const float* cosb = (const float*)d_in[1];
    const float* sinb = (const float*)d_in[2];
    const float* kci  = (const float*)d_in[3];
    const float* vci  = (const float*)d_in[4];
    const int*   slot = (const int*)d_in[5];
    const float* Wqkv = (const float*)d_in[6];
    const float* bqkv = (const float*)d_in[7];
    const float* Wo   = (const float*)d_in[8];

    float* out = (float*)d_out;
    float* kc  = out + OUT_ELEMS;
    float* vc  = kc + CACHE_ELEMS;

    float* qkv;  cudaGetSymbolAddress((void**)&qkv,  g_qkv);
    float* attn; cudaGetSymbolAddress((void**)&attn, g_attn);

    cudaFuncSetAttribute(attn_kernel,
                         cudaFuncAttributeMaxDynamicSharedMemorySize,
                         ATT_SMEM_FLOATS * (int)sizeof(float));
    cudaFuncSetAttribute(gemm_mma_kernel,
                         cudaFuncAttributeMaxDynamicSharedMemorySize,
                         G_SMEM_FLOATS * (int)sizeof(float));

    // 1. seed caches with the input caches
    cudaMemcpyAsync(kc, kci, CACHE_ELEMS * sizeof(float), cudaMemcpyDeviceToDevice);
    cudaMemcpyAsync(vc, vci, CACHE_ELEMS * sizeof(float), cudaMemcpyDeviceToDevice);

    // 2. QKV projection (tf32 mma.sync)
    {
        dim3 grid(NQKV / 128, Tn / 128);
        gemm_mma_kernel<<<grid, 256, G_SMEM_FLOATS * sizeof(float)>>>(
            x, Wqkv, bqkv, qkv, Tn, NQKV, HID);
    }

    // 3. RoPE in place + cache scatter
    rope_scatter_kernel<<<Tn, 256>>>(qkv, cosb, sinb, slot, kc, vc);

    // 4. causal GQA flash attention
    {
        dim3 grid(Sc / 64, Hq, Bc);
        dim3 blk(16, 16);
        attn_kernel<<<grid, blk, ATT_SMEM_FLOATS * sizeof(float)>>>(qkv, attn);
    }

    // 5. output projection (tf32 mma.sync)
    {
        dim3 grid(HID / 128, Tn / 128);
        gemm_mma_kernel<<<grid, 256, G_SMEM_FLOATS * sizeof(float)>>>(
            attn, Wo, nullptr, out, Tn, HID, HID);
    }
}

// round 4
// speedup vs baseline: 4.3445x; 2.9184x over previous
#include <cuda_runtime.h>
#include <cuda_bf16.h>
#include <cstdint>
#include <math.h>

// Problem constants
#define Hq    12
#define HKV   2
#define NG    6          // Hq / HKV
#define Dh    128
#define HID   1536
#define Bc    4
#define Sc    2048
#define Tn    (Bc*Sc)    // 8192 tokens
#define NQKV  2048       // Hq*Dh + 2*HKV*Dh
#define NSLOTS 16384
#define OUT_ELEMS   ((size_t)Tn*HID)          // 12582912
#define CACHE_ELEMS ((size_t)NSLOTS*HKV*Dh)   // 4194304

// Scratch (device globals; no runtime allocation allowed)
__device__ float g_qkv[(size_t)Tn * NQKV];    // 67 MB
__device__ float g_attn[(size_t)Tn * HID];    // 50 MB

// ===========================================================================
// TF32 helpers (portable to plain sm_103 target: no 'a'-gated instructions)
// ===========================================================================
__device__ __forceinline__ float to_tf32(float x) {
    float y;
    asm("cvt.rna.tf32.f32 %0, %1;" : "=f"(y) : "f"(x));
    return y;
}

__device__ __forceinline__ void mma_tf32_16x8x8(
    float& d0, float& d1, float& d2, float& d3,
    float a0, float a1, float a2, float a3,
    float b0, float b1)
{
    uint32_t A0 = __float_as_uint(a0), A1 = __float_as_uint(a1);
    uint32_t A2 = __float_as_uint(a2), A3 = __float_as_uint(a3);
    uint32_t B0 = __float_as_uint(b0), B1 = __float_as_uint(b1);
    asm volatile(
        "mma.sync.aligned.m16n8k8.row.col.f32.tf32.tf32.f32 "
        "{%0,%1,%2,%3}, {%4,%5,%6,%7}, {%8,%9}, {%0,%1,%2,%3};"
        : "+f"(d0), "+f"(d1), "+f"(d2), "+f"(d3)
        : "r"(A0), "r"(A1), "r"(A2), "r"(A3), "r"(B0), "r"(B1));
}

// ===========================================================================
// TF32 tensor-core GEMM: C[M,N] = A[M,K] @ B[N,K]^T (+ bias[N])
// (unchanged from round 3 — validated)
// ===========================================================================
#define GSTR 36
#define GBUF (128 * GSTR)
#define G_SMEM_FLOATS (4 * GBUF)

__global__ __launch_bounds__(256, 2) void gemm_mma_kernel(
    const float* __restrict__ A, const float* __restrict__ Bw,
    const float* __restrict__ bias, float* __restrict__ C,
    int M, int N, int K)
{
    extern __shared__ float smem[];
    float* As = smem;
    float* Bs = smem + 2 * GBUF;

    const int tid  = threadIdx.x;
    const int wid  = tid >> 5;
    const int lane = tid & 31;
    const int gid  = lane >> 2;
    const int tig  = lane & 3;

    const int m0 = blockIdx.y * 128;
    const int n0 = blockIdx.x * 128;
    const int wm0 = (wid >> 2) * 64;
    const int wn0 = (wid & 3) * 32;

    float4 ar[4], br[4];

    float acc[4][4][4];
#pragma unroll
    for (int mi = 0; mi < 4; mi++)
#pragma unroll
        for (int ni = 0; ni < 4; ni++)
#pragma unroll
            for (int r = 0; r < 4; r++) acc[mi][ni][r] = 0.f;

    const int nchunks = K >> 5;

#pragma unroll
    for (int i = 0; i < 4; i++) {
        const int idx = tid + i * 256;
        const int r  = idx >> 3;
        const int cg = (idx & 7) << 2;
        ar[i] = *(const float4*)(A  + (size_t)(m0 + r) * K + cg);
        br[i] = *(const float4*)(Bw + (size_t)(n0 + r) * K + cg);
    }
#pragma unroll
    for (int i = 0; i < 4; i++) {
        const int idx = tid + i * 256;
        const int r  = idx >> 3;
        const int cg = (idx & 7) << 2;
        float* pa = As + r * GSTR + cg;
        pa[0] = to_tf32(ar[i].x); pa[1] = to_tf32(ar[i].y);
        pa[2] = to_tf32(ar[i].z); pa[3] = to_tf32(ar[i].w);
        float* pb = Bs + r * GSTR + cg;
        pb[0] = to_tf32(br[i].x); pb[1] = to_tf32(br[i].y);
        pb[2] = to_tf32(br[i].z); pb[3] = to_tf32(br[i].w);
    }
    __syncthreads();

    int p = 0;
    for (int c = 0; c < nchunks; c++) {
        const bool more = (c + 1) < nchunks;
        if (more) {
            const int kc = (c + 1) << 5;
#pragma unroll
            for (int i = 0; i < 4; i++) {
                const int idx = tid + i * 256;
                const int r  = idx >> 3;
                const int cg = (idx & 7) << 2;
                ar[i] = *(const float4*)(A  + (size_t)(m0 + r) * K + kc + cg);
                br[i] = *(const float4*)(Bw + (size_t)(n0 + r) * K + kc + cg);
            }
        }

        const float* Ab = As + p * GBUF;
        const float* Bb = Bs + p * GBUF;
#pragma unroll
        for (int ks = 0; ks < 4; ks++) {
            const int kk = ks * 8;
            float afr[4][4];
#pragma unroll
            for (int mi = 0; mi < 4; mi++) {
                const int r = wm0 + mi * 16 + gid;
                const int cA = kk + tig;
                afr[mi][0] = Ab[r * GSTR + cA];
                afr[mi][1] = Ab[(r + 8) * GSTR + cA];
                afr[mi][2] = Ab[r * GSTR + cA + 4];
                afr[mi][3] = Ab[(r + 8) * GSTR + cA + 4];
            }
#pragma unroll
            for (int ni = 0; ni < 4; ni++) {
                const int rB = wn0 + ni * 8 + gid;
                const int cB = kk + tig;
                const float b0 = Bb[rB * GSTR + cB];
                const float b1 = Bb[rB * GSTR + cB + 4];
#pragma unroll
                for (int mi = 0; mi < 4; mi++) {
                    mma_tf32_16x8x8(acc[mi][ni][0], acc[mi][ni][1],
                                    acc[mi][ni][2], acc[mi][ni][3],
                                    afr[mi][0], afr[mi][1], afr[mi][2], afr[mi][3],
                                    b0, b1);
                }
            }
        }

        if (more) {
            float* Aw = As + (p ^ 1) * GBUF;
            float* Bww = Bs + (p ^ 1) * GBUF;
#pragma unroll
            for (int i = 0; i < 4; i++) {
                const int idx = tid + i * 256;
                const int r  = idx >> 3;
                const int cg = (idx & 7) << 2;
                float* pa = Aw + r * GSTR + cg;
                pa[0] = to_tf32(ar[i].x); pa[1] = to_tf32(ar[i].y);
                pa[2] = to_tf32(ar[i].z); pa[3] = to_tf32(ar[i].w);
                float* pb = Bww + r * GSTR + cg;
                pb[0] = to_tf32(br[i].x); pb[1] = to_tf32(br[i].y);
                pb[2] = to_tf32(br[i].z); pb[3] = to_tf32(br[i].w);
            }
        }
        __syncthreads();
        p ^= 1;
    }

#pragma unroll
    for (int mi = 0; mi < 4; mi++) {
        const int row = m0 + wm0 + mi * 16 + gid;
#pragma unroll
        for (int ni = 0; ni < 4; ni++) {
            const int col = n0 + wn0 + ni * 8 + 2 * tig;
            float b0 = 0.f, b1 = 0.f;
            if (bias) { b0 = bias[col]; b1 = bias[col + 1]; }
            float2 v0 = make_float2(acc[mi][ni][0] + b0, acc[mi][ni][1] + b1);
            float2 v1 = make_float2(acc[mi][ni][2] + b0, acc[mi][ni][3] + b1);
            *(float2*)(C + (size_t)row * N + col)       = v0;
            *(float2*)(C + (size_t)(row + 8) * N + col) = v1;
        }
    }
}

// ---------------------------------------------------------------------------
// RoPE (in place on g_qkv q,k heads) + scatter rotated k and raw v to caches.
// ---------------------------------------------------------------------------
__global__ void rope_scatter_kernel(float* __restrict__ qkv,
                                    const float* __restrict__ cosb,
                                    const float* __restrict__ sinb,
                                    const int* __restrict__ slot,
                                    float* __restrict__ kc,
                                    float* __restrict__ vc) {
    const int r = blockIdx.x;
    float* row = qkv + (size_t)r * NQKV;
    const float* cr = cosb + (size_t)r * Dh;
    const float* sr = sinb + (size_t)r * Dh;
    const int s = slot[r];

    for (int idx = threadIdx.x; idx < 14 * 64; idx += blockDim.x) {
        const int head = idx >> 6;
        const int d = idx & 63;
        float* hp = row + head * Dh;
        const float x1 = hp[d], x2 = hp[d + 64];
        const float c1 = cr[d], s1 = sr[d];
        const float c2 = cr[d + 64], s2 = sr[d + 64];
        const float o1 = x1 * c1 - x2 * s1;
        const float o2 = x2 * c2 + x1 * s2;
        hp[d] = o1;
        hp[d + 64] = o2;
        if (head >= Hq) {
            const int kh = head - Hq;
            float* kdst = kc + ((size_t)s * HKV + kh) * Dh;
            kdst[d] = o1;
            kdst[d + 64] = o2;
        }
    }
    for (int idx = threadIdx.x; idx < HKV * Dh; idx += blockDim.x) {
        vc[(size_t)s * (HKV * Dh) + idx] = row[Hq * Dh + HKV * Dh + idx];
    }
}

// ===========================================================================
// Tensor-core causal GQA flash attention (tf32 mma.sync).
// CTA: 128-query tile for one (head, batch). 512 threads = 16 warps (8M x 2N).
// Inner loop over 64-key tiles.
//   QK: warp computes m16 x n32 (4 n-tiles), k = 128 (16 k-steps).
//   PV: warp computes m16 x n64 (8 n-tiles), k = 64  (8 k-steps).
// ===========================================================================
#define AQSTR 132       // Q smem stride  (banks 4g+t distinct)
#define AKSTR 132       // K smem stride
#define AVSTR 136       // V smem stride  (banks 8t+g distinct for B-frag)
#define ASSTR 68        // scores stride
#define ATT_Q_FL   (128 * AQSTR)
#define ATT_K_FL   (64 * AKSTR)
#define ATT_V_FL   (64 * AVSTR)
#define ATT_S_FL   (128 * ASSTR)
#define ATT2_SMEM_FLOATS (ATT_Q_FL + ATT_K_FL + ATT_V_FL + ATT_S_FL + 3 * 128)

__global__ __launch_bounds__(512) void attn_mma_kernel(
    const float* __restrict__ qkv, float* __restrict__ out)
{
    extern __shared__ float sm[];
    float* Qs = sm;
    float* Ks = Qs + ATT_Q_FL;
    float* Vs = Ks + ATT_K_FL;
    float* Ss = Vs + ATT_V_FL;
    float* mrow = Ss + ATT_S_FL;
    float* lrow = mrow + 128;
    float* arow = lrow + 128;

    const int qt = (gridDim.x - 1) - blockIdx.x;   // heavy tiles first
    const int h = blockIdx.y, b = blockIdx.z;
    const int kh = h / NG;
    const int tid = threadIdx.x;
    const int wid = tid >> 5;
    const int lane = tid & 31;
    const int gid = lane >> 2;
    const int tig = lane & 3;
    const int wm = wid >> 1;          // 0..7 -> 16-row strip
    const int wn = wid & 1;           // 0..1
    const int q0 = qt * 128;
    const int rowbase = b * Sc;
    const float scale = 0.08838834764831845f;   // 1/sqrt(128)

    // --- load Q tile (tf32-converted) ---
    for (int i = tid; i < 128 * 32; i += 512) {
        const int r = i >> 5;
        const int col = (i & 31) << 2;
        float4 v = *(const float4*)(qkv + (size_t)(rowbase + q0 + r) * NQKV + h * Dh + col);
        float* p = Qs + r * AQSTR + col;
        p[0] = to_tf32(v.x); p[1] = to_tf32(v.y);
        p[2] = to_tf32(v.z); p[3] = to_tf32(v.w);
    }
    if (tid < 128) { mrow[tid] = -1e30f; lrow[tid] = 0.f; }

    float oacc[8][4];
#pragma unroll
    for (int nt = 0; nt < 8; nt++)
#pragma unroll
        for (int r = 0; r < 4; r++) oacc[nt][r] = 0.f;

    __syncthreads();

    const int nkt = 2 * qt + 2;
    for (int kt = 0; kt < nkt; kt++) {
        const int k0 = kt * 64;

        // --- load K/V tile (tf32-converted) ---
        for (int i = tid; i < 64 * 32; i += 512) {
            const int r = i >> 5;
            const int col = (i & 31) << 2;
            const size_t rb = (size_t)(rowbase + k0 + r) * NQKV + Hq * Dh;
            float4 kv = *(const float4*)(qkv + rb + kh * Dh + col);
            float* pk = Ks + r * AKSTR + col;
            pk[0] = to_tf32(kv.x); pk[1] = to_tf32(kv.y);
            pk[2] = to_tf32(kv.z); pk[3] = to_tf32(kv.w);
            float4 vv = *(const float4*)(qkv + rb + HKV * Dh + kh * Dh + col);
            float* pv = Vs + r * AVSTR + col;
            pv[0] = to_tf32(vv.x); pv[1] = to_tf32(vv.y);
            pv[2] = to_tf32(vv.z); pv[3] = to_tf32(vv.w);
        }
        __syncthreads();

        // --- QK^T: warp m16 x n32, k=128 ---
        float sacc[4][4];
#pragma unroll
        for (int nt = 0; nt < 4; nt++)
#pragma unroll
            for (int r = 0; r < 4; r++) sacc[nt][r] = 0.f;

#pragma unroll
        for (int kk = 0; kk < 16; kk++) {
            const int kc = kk * 8;
            const int rA = wm * 16 + gid;
            const float a0 = Qs[rA * AQSTR + kc + tig];
            const float a1 = Qs[(rA + 8) * AQSTR + kc + tig];
            const float a2 = Qs[rA * AQSTR + kc + tig + 4];
            const float a3 = Qs[(rA + 8) * AQSTR + kc + tig + 4];
#pragma unroll
            for (int nt = 0; nt < 4; nt++) {
                const int rB = wn * 32 + nt * 8 + gid;
                const float b0 = Ks[rB * AKSTR + kc + tig];
                const float b1 = Ks[rB * AKSTR + kc + tig + 4];
                mma_tf32_16x8x8(sacc[nt][0], sacc[nt][1], sacc[nt][2], sacc[nt][3],
                                a0, a1, a2, a3, b0, b1);
            }
        }

        // --- scale + causal mask + write scores ---
        {
            const int r0 = wm * 16 + gid;
            const int r1 = r0 + 8;
            const int qr0 = q0 + r0, qr1 = q0 + r1;
#pragma unroll
            for (int nt = 0; nt < 4; nt++) {
                const int col = wn * 32 + nt * 8 + 2 * tig;
                const int gc = k0 + col;
                Ss[r0 * ASSTR + col]     = (gc     <= qr0) ? sacc[nt][0] * scale : -1e30f;
                Ss[r0 * ASSTR + col + 1] = (gc + 1 <= qr0) ? sacc[nt][1] * scale : -1e30f;
                Ss[r1 * ASSTR + col]     = (gc     <= qr1) ? sacc[nt][2] * scale : -1e30f;
                Ss[r1 * ASSTR + col + 1] = (gc + 1 <= qr1) ? sacc[nt][3] * scale : -1e30f;
            }
        }
        __syncthreads();

        // --- online softmax: 4 threads per row, 16 cols each ---
        {
            const int row = tid >> 2;
            const int part = tid & 3;
            float* sp = Ss + row * ASSTR + part * 16;
            float4 v0 = *(float4*)(sp);
            float4 v1 = *(float4*)(sp + 4);
            float4 v2 = *(float4*)(sp + 8);
            float4 v3 = *(float4*)(sp + 12);
            float mx = fmaxf(fmaxf(fmaxf(v0.x, v0.y), fmaxf(v0.z, v0.w)),
                             fmaxf(fmaxf(v1.x, v1.y), fmaxf(v1.z, v1.w)));
            mx = fmaxf(mx, fmaxf(fmaxf(fmaxf(v2.x, v2.y), fmaxf(v2.z, v2.w)),
                                 fmaxf(fmaxf(v3.x, v3.y), fmaxf(v3.z, v3.w))));
            mx = fmaxf(mx, __shfl_xor_sync(0xFFFFFFFFu, mx, 1));
            mx = fmaxf(mx, __shfl_xor_sync(0xFFFFFFFFu, mx, 2));
            const float mo = mrow[row];
            const float mn = fmaxf(mo, mx);
            const float alpha = __expf(mo - mn);
            v0.x = __expf(v0.x - mn); v0.y = __expf(v0.y - mn);
            v0.z = __expf(v0.z - mn); v0.w = __expf(v0.w - mn);
            v1.x = __expf(v1.x - mn); v1.y = __expf(v1.y - mn);
            v1.z = __expf(v1.z - mn); v1.w = __expf(v1.w - mn);
            v2.x = __expf(v2.x - mn); v2.y = __expf(v2.y - mn);
            v2.z = __expf(v2.z - mn); v2.w = __expf(v2.w - mn);
            v3.x = __expf(v3.x - mn); v3.y = __expf(v3.y - mn);
            v3.z = __expf(v3.z - mn); v3.w = __expf(v3.w - mn);
            *(float4*)(sp)      = v0;
            *(float4*)(sp + 4)  = v1;
            *(float4*)(sp + 8)  = v2;
            *(float4*)(sp + 12) = v3;
            float s = (v0.x + v0.y + v0.z + v0.w) + (v1.x + v1.y + v1.z + v1.w)
                    + (v2.x + v2.y + v2.z + v2.w) + (v3.x + v3.y + v3.z + v3.w);
            s += __shfl_xor_sync(0xFFFFFFFFu, s, 1);
            s += __shfl_xor_sync(0xFFFFFFFFu, s, 2);
            if (part == 0) {
                mrow[row] = mn;
                lrow[row] = lrow[row] * alpha + s;
                arow[row] = alpha;
            }
        }
        __syncthreads();

        // --- rescale O accumulators and P @ V ---
        {
            const float a0 = arow[wm * 16 + gid];
            const float a1 = arow[wm * 16 + gid + 8];
#pragma unroll
            for (int nt = 0; nt < 8; nt++) {
                oacc[nt][0] *= a0; oacc[nt][1] *= a0;
                oacc[nt][2] *= a1; oacc[nt][3] *= a1;
            }
#pragma unroll
            for (int ks = 0; ks < 8; ks++) {
                const int kc = ks * 8;
                const int rA = wm * 16 + gid;
                const float a0f = to_tf32(Ss[rA * ASSTR + kc + tig]);
                const float a1f = to_tf32(Ss[(rA + 8) * ASSTR + kc + tig]);
                const float a2f = to_tf32(Ss[rA * ASSTR + kc + tig + 4]);
                const float a3f = to_tf32(Ss[(rA + 8) * ASSTR + kc + tig + 4]);
#pragma unroll
                for (int nt = 0; nt < 8; nt++) {
                    const int n0 = wn * 64 + nt * 8;
                    const float b0 = Vs[(kc + tig) * AVSTR + n0 + gid];
                    const float b1 = Vs[(kc + tig + 4) * AVSTR + n0 + gid];
                    mma_tf32_16x8x8(oacc[nt][0], oacc[nt][1], oacc[nt][2], oacc[nt][3],
                                    a0f, a1f, a2f, a3f, b0, b1);
                }
            }
        }
        __syncthreads();   // protect K/V/S before next iteration's overwrite
    }

    // --- normalize + write out ---
    {
        const int r0 = wm * 16 + gid;
        const int r1 = r0 + 8;
        const float inv0 = 1.0f / lrow[r0];
        const float inv1 = 1.0f / lrow[r1];
        const size_t ob0 = (size_t)(rowbase + q0 + r0) * HID + h * Dh;
        const size_t ob1 = (size_t)(rowbase + q0 + r1) * HID + h * Dh;
#pragma unroll
        for (int nt = 0; nt < 8; nt++) {
            const int col = wn * 64 + nt * 8 + 2 * tig;
            *(float2*)(out + ob0 + col) = make_float2(oacc[nt][0] * inv0, oacc[nt][1] * inv0);
            *(float2*)(out + ob1 + col) = make_float2(oacc[nt][2] * inv1, oacc[nt][3] * inv1);
        }
    }
}

// ---------------------------------------------------------------------------
// kernel_launch
// ---------------------------------------------------------------------------
extern "C" void kernel_launch(void* const* d_in, const int* in_sizes, int n_in,
                              void* d_out, int out_size) {
    const float* x    = (const float*)d_in[0];
    const float* cosb = (const float*)d_in[1];
    const float* sinb = (const float*)d_in[2];
    const float* kci  = (const float*)d_in[3];
    const float* vci  = (const float*)d_in[4];
    const int*   slot = (const int*)d_in[5];
    const float* Wqkv = (const float*)d_in[6];
    const float* bqkv = (const float*)d_in[7];
    const float* Wo   = (const float*)d_in[8];

    float* out = (float*)d_out;
    float* kc  = out + OUT_ELEMS;
    float* vc  = kc + CACHE_ELEMS;

    float* qkv;  cudaGetSymbolAddress((void**)&qkv,  g_qkv);
    float* attn; cudaGetSymbolAddress((void**)&attn, g_attn);

    cudaFuncSetAttribute(attn_mma_kernel,
                         cudaFuncAttributeMaxDynamicSharedMemorySize,
                         ATT2_SMEM_FLOATS * (int)sizeof(float));
    cudaFuncSetAttribute(gemm_mma_kernel,
                         cudaFuncAttributeMaxDynamicSharedMemorySize,
                         G_SMEM_FLOATS * (int)sizeof(float));

    // 1. seed caches with the input caches
    cudaMemcpyAsync(kc, kci, CACHE_ELEMS * sizeof(float), cudaMemcpyDeviceToDevice);
    cudaMemcpyAsync(vc, vci, CACHE_ELEMS * sizeof(float), cudaMemcpyDeviceToDevice);

    // 2. QKV projection (tf32 mma.sync)
    {
        dim3 grid(NQKV / 128, Tn / 128);
        gemm_mma_kernel<<<grid, 256, G_SMEM_FLOATS * sizeof(float)>>>(
            x, Wqkv, bqkv, qkv, Tn, NQKV, HID);
    }

    // 3. RoPE in place + cache scatter
    rope_scatter_kernel<<<Tn, 256>>>(qkv, cosb, sinb, slot, kc, vc);

    // 4. causal GQA flash attention (tensor cores)
    {
        dim3 grid(Sc / 128, Hq, Bc);
        attn_mma_kernel<<<grid, 512, ATT2_SMEM_FLOATS * sizeof(float)>>>(qkv, attn);
    }

    // 5. output projection (tf32 mma.sync)
    {
        dim3 grid(HID / 128, Tn / 128);
        gemm_mma_kernel<<<grid, 256, G_SMEM_FLOATS * sizeof(float)>>>(
            attn, Wo, nullptr, out, Tn, HID, HID);
    }
}